// round 7
// baseline (speedup 1.0000x reference)
#include <cuda_runtime.h>
#include <math.h>
#include <stdint.h>

#define TEMP_INV 14.2857142857142857f   // 1/0.07
#define EPS_NORM 1e-12f

// Scratch accumulators (no device allocation allowed).
__device__ double g_total;
__device__ double g_count;
__device__ int    g_lab32;   // 1 => labels stored as int32, 0 => int64

__global__ void zero_accum_kernel() {
    g_total = 0.0;
    g_count = 0.0;
    g_lab32 = 0;
}

// If labels are int64 (values 0/1, little-endian), every odd int32 word is 0.
// If labels are int32, odd words are random labels -> some are 1.
__global__ void detect_label_kernel(const int* __restrict__ l32, int n_elems) {
    int idx = blockIdx.x * blockDim.x + threadIdx.x;
    int stride = blockDim.x * gridDim.x;
    int found = 0;
    for (int i = 2 * idx + 1; i < n_elems; i += 2 * stride)
        found |= l32[i];
    // warp-reduce to cut atomics
    #pragma unroll
    for (int off = 16; off > 0; off >>= 1)
        found |= __shfl_xor_sync(0xffffffffu, found, off);
    if ((threadIdx.x & 31) == 0 && found)
        atomicOr(&g_lab32, 1);
}

__global__ __launch_bounds__(256) void contrastive_loss_kernel(
    const float* __restrict__ emb,     // (B, 4, 1024)
    const int*   __restrict__ lab32,   // labels viewed as int32 words
    int B)
{
    const int lane   = threadIdx.x & 31;
    const int warpIn = threadIdx.x >> 5;               // warp within block (0..7)
    const int gwarp  = (blockIdx.x * blockDim.x + threadIdx.x) >> 5;
    const int nwarps = (gridDim.x * blockDim.x) >> 5;

    const int lstride = g_lab32 ? 1 : 2;   // int32 layout: stride 1; int64: low word every 2

    float loc_total = 0.0f;
    float loc_count = 0.0f;

    for (int b = gwarp; b < B; b += nwarps) {
        const float4* base = reinterpret_cast<const float4*>(emb + (size_t)b * 4096);

        // 10 unique gram-matrix accumulators
        float s00 = 0.f, s01 = 0.f, s02 = 0.f, s03 = 0.f;
        float s11 = 0.f, s12 = 0.f, s13 = 0.f;
        float s22 = 0.f, s23 = 0.f, s33 = 0.f;

        #pragma unroll
        for (int c = 0; c < 8; ++c) {
            float4 v0 = base[        c * 32 + lane];   // row 0 (1024 floats = 256 float4)
            float4 v1 = base[256 +   c * 32 + lane];   // row 1
            float4 v2 = base[512 +   c * 32 + lane];   // row 2
            float4 v3 = base[768 +   c * 32 + lane];   // row 3

            s00 += v0.x*v0.x + v0.y*v0.y + v0.z*v0.z + v0.w*v0.w;
            s01 += v0.x*v1.x + v0.y*v1.y + v0.z*v1.z + v0.w*v1.w;
            s02 += v0.x*v2.x + v0.y*v2.y + v0.z*v2.z + v0.w*v2.w;
            s03 += v0.x*v3.x + v0.y*v3.y + v0.z*v3.z + v0.w*v3.w;
            s11 += v1.x*v1.x + v1.y*v1.y + v1.z*v1.z + v1.w*v1.w;
            s12 += v1.x*v2.x + v1.y*v2.y + v1.z*v2.z + v1.w*v2.w;
            s13 += v1.x*v3.x + v1.y*v3.y + v1.z*v3.z + v1.w*v3.w;
            s22 += v2.x*v2.x + v2.y*v2.y + v2.z*v2.z + v2.w*v2.w;
            s23 += v2.x*v3.x + v2.y*v3.y + v2.z*v3.z + v2.w*v3.w;
            s33 += v3.x*v3.x + v3.y*v3.y + v3.z*v3.z + v3.w*v3.w;
        }

        // warp tree reduce for all 10 sums
        #pragma unroll
        for (int off = 16; off > 0; off >>= 1) {
            s00 += __shfl_xor_sync(0xffffffffu, s00, off);
            s01 += __shfl_xor_sync(0xffffffffu, s01, off);
            s02 += __shfl_xor_sync(0xffffffffu, s02, off);
            s03 += __shfl_xor_sync(0xffffffffu, s03, off);
            s11 += __shfl_xor_sync(0xffffffffu, s11, off);
            s12 += __shfl_xor_sync(0xffffffffu, s12, off);
            s13 += __shfl_xor_sync(0xffffffffu, s13, off);
            s22 += __shfl_xor_sync(0xffffffffu, s22, off);
            s23 += __shfl_xor_sync(0xffffffffu, s23, off);
            s33 += __shfl_xor_sync(0xffffffffu, s33, off);
        }

        if (lane == 0) {
            float S[4][4];
            S[0][0] = s00; S[0][1] = s01; S[0][2] = s02; S[0][3] = s03;
            S[1][0] = s01; S[1][1] = s11; S[1][2] = s12; S[1][3] = s13;
            S[2][0] = s02; S[2][1] = s12; S[2][2] = s22; S[2][3] = s23;
            S[3][0] = s03; S[3][1] = s13; S[3][2] = s23; S[3][3] = s33;

            float inv[4];
            #pragma unroll
            for (int i = 0; i < 4; ++i)
                inv[i] = 1.0f / fmaxf(sqrtf(S[i][i]), EPS_NORM);

            float E[4][4];
            #pragma unroll
            for (int i = 0; i < 4; ++i)
                #pragma unroll
                for (int j = 0; j < 4; ++j)
                    E[i][j] = expf(S[i][j] * inv[i] * inv[j] * TEMP_INV);

            int lab[4];
            #pragma unroll
            for (int i = 0; i < 4; ++i)
                lab[i] = lab32[((size_t)b * 4 + i) * lstride];   // 0 or 1

            int P = lab[0] + lab[1] + lab[2] + lab[3];
            bool valid = (P > 0) && (P < 4);

            if (valid) {
                if (P > 1) {
                    float ps = 0.f;
                    #pragma unroll
                    for (int i = 0; i < 4; ++i)
                        if (lab[i])
                            #pragma unroll
                            for (int j = 0; j < 4; ++j)
                                if (lab[j]) ps += E[i][j];
                    loc_total += -logf(ps / (float)(P * P));
                }
                #pragma unroll
                for (int i = 0; i < 4; ++i) {
                    if (lab[i]) {
                        float ns = 0.f;
                        #pragma unroll
                        for (int j = 0; j < 4; ++j)
                            if (!lab[j]) ns += E[i][j];
                        loc_total += log1pf(ns);
                    }
                }
                loc_count += (float)(P + (P > 1 ? 1 : 0));
            }
        }
    }

    // block reduction
    __shared__ float sh_total[8];
    __shared__ float sh_count[8];
    if (lane == 0) {
        sh_total[warpIn] = loc_total;
        sh_count[warpIn] = loc_count;
    }
    __syncthreads();
    if (threadIdx.x == 0) {
        double t = 0.0, c = 0.0;
        #pragma unroll
        for (int w = 0; w < 8; ++w) { t += (double)sh_total[w]; c += (double)sh_count[w]; }
        atomicAdd(&g_total, t);
        atomicAdd(&g_count, c);
    }
}

__global__ void finalize_kernel(float* out) {
    double c = g_count;
    out[0] = (float)(g_total / (c > 1.0 ? c : 1.0));
}

extern "C" void kernel_launch(void* const* d_in, const int* in_sizes, int n_in,
                              void* d_out, int out_size)
{
    const float* emb   = (const float*)d_in[0];
    const int*   lab32 = (const int*)d_in[1];
    int n_lab = in_sizes[1];          // B*4 label elements
    int B = n_lab / 4;

    zero_accum_kernel<<<1, 1>>>();
    detect_label_kernel<<<32, 256>>>(lab32, n_lab);
    contrastive_loss_kernel<<<2048, 256>>>(emb, lab32, B);
    finalize_kernel<<<1, 1>>>((float*)d_out);
}

// round 10
// speedup vs baseline: 1.0016x; 1.0016x over previous
#include <cuda_runtime.h>
#include <math.h>
#include <stdint.h>

#define TEMP_INV 14.2857142857142857f   // 1/0.07
#define EPS_NORM 1e-12f

// Scratch accumulators (no device allocation allowed).
__device__ double g_total;
__device__ double g_count;
__device__ int    g_lab32;   // 1 => labels stored as int32, 0 => int64

__global__ void zero_accum_kernel() {
    g_total = 0.0;
    g_count = 0.0;
    g_lab32 = 0;
}

// If labels are int64 (values 0/1, little-endian), every odd int32 word is 0.
// If labels are int32, odd words are random labels -> some are 1.
__global__ void detect_label_kernel(const int* __restrict__ l32, int n_elems) {
    int idx = blockIdx.x * blockDim.x + threadIdx.x;
    int stride = blockDim.x * gridDim.x;
    int found = 0;
    for (int i = 2 * idx + 1; i < n_elems; i += 2 * stride)
        found |= l32[i];
    // warp-reduce to cut atomics
    #pragma unroll
    for (int off = 16; off > 0; off >>= 1)
        found |= __shfl_xor_sync(0xffffffffu, found, off);
    if ((threadIdx.x & 31) == 0 && found)
        atomicOr(&g_lab32, 1);
}

__global__ __launch_bounds__(256) void contrastive_loss_kernel(
    const float* __restrict__ emb,     // (B, 4, 1024)
    const int*   __restrict__ lab32,   // labels viewed as int32 words
    int B)
{
    const int lane   = threadIdx.x & 31;
    const int warpIn = threadIdx.x >> 5;               // warp within block (0..7)
    const int gwarp  = (blockIdx.x * blockDim.x + threadIdx.x) >> 5;
    const int nwarps = (gridDim.x * blockDim.x) >> 5;

    const int lstride = g_lab32 ? 1 : 2;   // int32 layout: stride 1; int64: low word every 2

    float loc_total = 0.0f;
    float loc_count = 0.0f;

    for (int b = gwarp; b < B; b += nwarps) {
        const float4* base = reinterpret_cast<const float4*>(emb + (size_t)b * 4096);

        // 10 unique gram-matrix accumulators
        float s00 = 0.f, s01 = 0.f, s02 = 0.f, s03 = 0.f;
        float s11 = 0.f, s12 = 0.f, s13 = 0.f;
        float s22 = 0.f, s23 = 0.f, s33 = 0.f;

        #pragma unroll
        for (int c = 0; c < 8; ++c) {
            float4 v0 = base[        c * 32 + lane];   // row 0 (1024 floats = 256 float4)
            float4 v1 = base[256 +   c * 32 + lane];   // row 1
            float4 v2 = base[512 +   c * 32 + lane];   // row 2
            float4 v3 = base[768 +   c * 32 + lane];   // row 3

            s00 += v0.x*v0.x + v0.y*v0.y + v0.z*v0.z + v0.w*v0.w;
            s01 += v0.x*v1.x + v0.y*v1.y + v0.z*v1.z + v0.w*v1.w;
            s02 += v0.x*v2.x + v0.y*v2.y + v0.z*v2.z + v0.w*v2.w;
            s03 += v0.x*v3.x + v0.y*v3.y + v0.z*v3.z + v0.w*v3.w;
            s11 += v1.x*v1.x + v1.y*v1.y + v1.z*v1.z + v1.w*v1.w;
            s12 += v1.x*v2.x + v1.y*v2.y + v1.z*v2.z + v1.w*v2.w;
            s13 += v1.x*v3.x + v1.y*v3.y + v1.z*v3.z + v1.w*v3.w;
            s22 += v2.x*v2.x + v2.y*v2.y + v2.z*v2.z + v2.w*v2.w;
            s23 += v2.x*v3.x + v2.y*v3.y + v2.z*v3.z + v2.w*v3.w;
            s33 += v3.x*v3.x + v3.y*v3.y + v3.z*v3.z + v3.w*v3.w;
        }

        // warp tree reduce for all 10 sums
        #pragma unroll
        for (int off = 16; off > 0; off >>= 1) {
            s00 += __shfl_xor_sync(0xffffffffu, s00, off);
            s01 += __shfl_xor_sync(0xffffffffu, s01, off);
            s02 += __shfl_xor_sync(0xffffffffu, s02, off);
            s03 += __shfl_xor_sync(0xffffffffu, s03, off);
            s11 += __shfl_xor_sync(0xffffffffu, s11, off);
            s12 += __shfl_xor_sync(0xffffffffu, s12, off);
            s13 += __shfl_xor_sync(0xffffffffu, s13, off);
            s22 += __shfl_xor_sync(0xffffffffu, s22, off);
            s23 += __shfl_xor_sync(0xffffffffu, s23, off);
            s33 += __shfl_xor_sync(0xffffffffu, s33, off);
        }

        if (lane == 0) {
            float S[4][4];
            S[0][0] = s00; S[0][1] = s01; S[0][2] = s02; S[0][3] = s03;
            S[1][0] = s01; S[1][1] = s11; S[1][2] = s12; S[1][3] = s13;
            S[2][0] = s02; S[2][1] = s12; S[2][2] = s22; S[2][3] = s23;
            S[3][0] = s03; S[3][1] = s13; S[3][2] = s23; S[3][3] = s33;

            float inv[4];
            #pragma unroll
            for (int i = 0; i < 4; ++i)
                inv[i] = 1.0f / fmaxf(sqrtf(S[i][i]), EPS_NORM);

            float E[4][4];
            #pragma unroll
            for (int i = 0; i < 4; ++i)
                #pragma unroll
                for (int j = 0; j < 4; ++j)
                    E[i][j] = expf(S[i][j] * inv[i] * inv[j] * TEMP_INV);

            int lab[4];
            #pragma unroll
            for (int i = 0; i < 4; ++i)
                lab[i] = lab32[((size_t)b * 4 + i) * lstride];   // 0 or 1

            int P = lab[0] + lab[1] + lab[2] + lab[3];
            bool valid = (P > 0) && (P < 4);

            if (valid) {
                if (P > 1) {
                    float ps = 0.f;
                    #pragma unroll
                    for (int i = 0; i < 4; ++i)
                        if (lab[i])
                            #pragma unroll
                            for (int j = 0; j < 4; ++j)
                                if (lab[j]) ps += E[i][j];
                    loc_total += -logf(ps / (float)(P * P));
                }
                #pragma unroll
                for (int i = 0; i < 4; ++i) {
                    if (lab[i]) {
                        float ns = 0.f;
                        #pragma unroll
                        for (int j = 0; j < 4; ++j)
                            if (!lab[j]) ns += E[i][j];
                        loc_total += log1pf(ns);
                    }
                }
                loc_count += (float)(P + (P > 1 ? 1 : 0));
            }
        }
    }

    // block reduction
    __shared__ float sh_total[8];
    __shared__ float sh_count[8];
    if (lane == 0) {
        sh_total[warpIn] = loc_total;
        sh_count[warpIn] = loc_count;
    }
    __syncthreads();
    if (threadIdx.x == 0) {
        double t = 0.0, c = 0.0;
        #pragma unroll
        for (int w = 0; w < 8; ++w) { t += (double)sh_total[w]; c += (double)sh_count[w]; }
        atomicAdd(&g_total, t);
        atomicAdd(&g_count, c);
    }
}

__global__ void finalize_kernel(float* out) {
    double c = g_count;
    out[0] = (float)(g_total / (c > 1.0 ? c : 1.0));
}

extern "C" void kernel_launch(void* const* d_in, const int* in_sizes, int n_in,
                              void* d_out, int out_size)
{
    const float* emb   = (const float*)d_in[0];
    const int*   lab32 = (const int*)d_in[1];
    int n_lab = in_sizes[1];          // B*4 label elements
    int B = n_lab / 4;

    zero_accum_kernel<<<1, 1>>>();
    detect_label_kernel<<<32, 256>>>(lab32, n_lab);
    contrastive_loss_kernel<<<2048, 256>>>(emb, lab32, B);
    finalize_kernel<<<1, 1>>>((float*)d_out);
}

// round 14
// speedup vs baseline: 1.0151x; 1.0134x over previous
#include <cuda_runtime.h>
#include <math.h>
#include <stdint.h>

#define TEMP_INV 14.2857142857142857f   // 1/0.07
#define EPS_NORM 1e-12f

// Scratch accumulators (no device allocation allowed).
__device__ double g_total;
__device__ double g_count;
__device__ int    g_lab32;   // 1 => labels stored as int32, 0 => int64

__global__ void zero_accum_kernel() {
    g_total = 0.0;
    g_count = 0.0;
    g_lab32 = 0;
}

// If labels are int64 (values 0/1, little-endian), every odd int32 word is 0.
// If labels are int32, odd words are random labels -> some are 1.
__global__ void detect_label_kernel(const int* __restrict__ l32, int n_elems) {
    int idx = blockIdx.x * blockDim.x + threadIdx.x;
    int stride = blockDim.x * gridDim.x;
    int found = 0;
    for (int i = 2 * idx + 1; i < n_elems; i += 2 * stride)
        found |= l32[i];
    // warp-reduce to cut atomics
    #pragma unroll
    for (int off = 16; off > 0; off >>= 1)
        found |= __shfl_xor_sync(0xffffffffu, found, off);
    if ((threadIdx.x & 31) == 0 && found)
        atomicOr(&g_lab32, 1);
}

__global__ __launch_bounds__(256) void contrastive_loss_kernel(
    const float* __restrict__ emb,     // (B, 4, 1024)
    const int*   __restrict__ lab32,   // labels viewed as int32 words
    int B)
{
    const int lane   = threadIdx.x & 31;
    const int warpIn = threadIdx.x >> 5;               // warp within block (0..7)
    const int gwarp  = (blockIdx.x * blockDim.x + threadIdx.x) >> 5;
    const int nwarps = (gridDim.x * blockDim.x) >> 5;

    const int lstride = g_lab32 ? 1 : 2;   // int32 layout: stride 1; int64: low word every 2

    float loc_total = 0.0f;
    float loc_count = 0.0f;

    for (int b = gwarp; b < B; b += nwarps) {
        const float4* base = reinterpret_cast<const float4*>(emb + (size_t)b * 4096);

        // 10 unique gram-matrix accumulators
        float s00 = 0.f, s01 = 0.f, s02 = 0.f, s03 = 0.f;
        float s11 = 0.f, s12 = 0.f, s13 = 0.f;
        float s22 = 0.f, s23 = 0.f, s33 = 0.f;

        #pragma unroll
        for (int c = 0; c < 8; ++c) {
            float4 v0 = base[        c * 32 + lane];   // row 0 (1024 floats = 256 float4)
            float4 v1 = base[256 +   c * 32 + lane];   // row 1
            float4 v2 = base[512 +   c * 32 + lane];   // row 2
            float4 v3 = base[768 +   c * 32 + lane];   // row 3

            s00 += v0.x*v0.x + v0.y*v0.y + v0.z*v0.z + v0.w*v0.w;
            s01 += v0.x*v1.x + v0.y*v1.y + v0.z*v1.z + v0.w*v1.w;
            s02 += v0.x*v2.x + v0.y*v2.y + v0.z*v2.z + v0.w*v2.w;
            s03 += v0.x*v3.x + v0.y*v3.y + v0.z*v3.z + v0.w*v3.w;
            s11 += v1.x*v1.x + v1.y*v1.y + v1.z*v1.z + v1.w*v1.w;
            s12 += v1.x*v2.x + v1.y*v2.y + v1.z*v2.z + v1.w*v2.w;
            s13 += v1.x*v3.x + v1.y*v3.y + v1.z*v3.z + v1.w*v3.w;
            s22 += v2.x*v2.x + v2.y*v2.y + v2.z*v2.z + v2.w*v2.w;
            s23 += v2.x*v3.x + v2.y*v3.y + v2.z*v3.z + v2.w*v3.w;
            s33 += v3.x*v3.x + v3.y*v3.y + v3.z*v3.z + v3.w*v3.w;
        }

        // warp tree reduce for all 10 sums
        #pragma unroll
        for (int off = 16; off > 0; off >>= 1) {
            s00 += __shfl_xor_sync(0xffffffffu, s00, off);
            s01 += __shfl_xor_sync(0xffffffffu, s01, off);
            s02 += __shfl_xor_sync(0xffffffffu, s02, off);
            s03 += __shfl_xor_sync(0xffffffffu, s03, off);
            s11 += __shfl_xor_sync(0xffffffffu, s11, off);
            s12 += __shfl_xor_sync(0xffffffffu, s12, off);
            s13 += __shfl_xor_sync(0xffffffffu, s13, off);
            s22 += __shfl_xor_sync(0xffffffffu, s22, off);
            s23 += __shfl_xor_sync(0xffffffffu, s23, off);
            s33 += __shfl_xor_sync(0xffffffffu, s33, off);
        }

        if (lane == 0) {
            float S[4][4];
            S[0][0] = s00; S[0][1] = s01; S[0][2] = s02; S[0][3] = s03;
            S[1][0] = s01; S[1][1] = s11; S[1][2] = s12; S[1][3] = s13;
            S[2][0] = s02; S[2][1] = s12; S[2][2] = s22; S[2][3] = s23;
            S[3][0] = s03; S[3][1] = s13; S[3][2] = s23; S[3][3] = s33;

            float inv[4];
            #pragma unroll
            for (int i = 0; i < 4; ++i)
                inv[i] = 1.0f / fmaxf(sqrtf(S[i][i]), EPS_NORM);

            float E[4][4];
            #pragma unroll
            for (int i = 0; i < 4; ++i)
                #pragma unroll
                for (int j = 0; j < 4; ++j)
                    E[i][j] = expf(S[i][j] * inv[i] * inv[j] * TEMP_INV);

            int lab[4];
            #pragma unroll
            for (int i = 0; i < 4; ++i)
                lab[i] = lab32[((size_t)b * 4 + i) * lstride];   // 0 or 1

            int P = lab[0] + lab[1] + lab[2] + lab[3];
            bool valid = (P > 0) && (P < 4);

            if (valid) {
                if (P > 1) {
                    float ps = 0.f;
                    #pragma unroll
                    for (int i = 0; i < 4; ++i)
                        if (lab[i])
                            #pragma unroll
                            for (int j = 0; j < 4; ++j)
                                if (lab[j]) ps += E[i][j];
                    loc_total += -logf(ps / (float)(P * P));
                }
                #pragma unroll
                for (int i = 0; i < 4; ++i) {
                    if (lab[i]) {
                        float ns = 0.f;
                        #pragma unroll
                        for (int j = 0; j < 4; ++j)
                            if (!lab[j]) ns += E[i][j];
                        loc_total += log1pf(ns);
                    }
                }
                loc_count += (float)(P + (P > 1 ? 1 : 0));
            }
        }
    }

    // block reduction
    __shared__ float sh_total[8];
    __shared__ float sh_count[8];
    if (lane == 0) {
        sh_total[warpIn] = loc_total;
        sh_count[warpIn] = loc_count;
    }
    __syncthreads();
    if (threadIdx.x == 0) {
        double t = 0.0, c = 0.0;
        #pragma unroll
        for (int w = 0; w < 8; ++w) { t += (double)sh_total[w]; c += (double)sh_count[w]; }
        atomicAdd(&g_total, t);
        atomicAdd(&g_count, c);
    }
}

__global__ void finalize_kernel(float* out) {
    double c = g_count;
    out[0] = (float)(g_total / (c > 1.0 ? c : 1.0));
}

extern "C" void kernel_launch(void* const* d_in, const int* in_sizes, int n_in,
                              void* d_out, int out_size)
{
    const float* emb   = (const float*)d_in[0];
    const int*   lab32 = (const int*)d_in[1];
    int n_lab = in_sizes[1];          // B*4 label elements
    int B = n_lab / 4;

    zero_accum_kernel<<<1, 1>>>();
    detect_label_kernel<<<32, 256>>>(lab32, n_lab);
    contrastive_loss_kernel<<<2048, 256>>>(emb, lab32, B);
    finalize_kernel<<<1, 1>>>((float*)d_out);
}